// round 1
// baseline (speedup 1.0000x reference)
#include <cuda_runtime.h>

// NeighborlistBruteNsq: out[p] = (r_ij, d_ij) * (d_ij <= 0.5), minimum-image
// wrapped in an orthogonal box. Pair index p -> (i, j) inverted analytically
// (i_pairs/j_pairs inputs are np.triu_indices and are NOT read -> saves 67 MB
// of HBM traffic; kernel is pure streaming-store bound at ~134 MB).

__global__ __launch_bounds__(256)
void nlist_kernel(const float* __restrict__ pos,
                  const float* __restrict__ boxv,
                  float4* __restrict__ out,
                  int n_pairs, int N)
{
    int p = blockIdx.x * blockDim.x + threadIdx.x;
    if (p >= n_pairs) return;

    // ---- invert upper-triangular (k=1) flat index: find i s.t. C(i) <= p < C(i+1)
    // C(i) = i*(2N-1-i)/2  (number of pairs with row < i)
    const int M = 2 * N - 1;
    float fm = (float)M;
    float disc = fmaxf(fm * fm - 8.0f * (float)p, 0.0f);
    float s = sqrtf(disc);
    int i = (int)((fm - s) * 0.5f);
    i = min(max(i, 0), N - 2);
    // fixup (fp32 estimate can be off by a few when disc cancels)
    #pragma unroll 1
    while (i < N - 2 && ((i + 1) * (M - (i + 1)) >> 1) <= p) ++i;
    #pragma unroll 1
    while (i > 0 && ((i * (M - i)) >> 1) > p) --i;
    int base = (i * (M - i)) >> 1;
    int j = i + 1 + (p - base);

    // ---- box lengths (orthogonal box: diagonal of box_vectors)
    float bx = __ldg(&boxv[0]);
    float by = __ldg(&boxv[4]);
    float bz = __ldg(&boxv[8]);
    float hx = bx * 0.5f, hy = by * 0.5f, hz = bz * 0.5f;

    // ---- gather positions (48 KB total -> L1 resident; j sequential within a run)
    float xi = __ldg(&pos[3 * i + 0]);
    float yi = __ldg(&pos[3 * i + 1]);
    float zi = __ldg(&pos[3 * i + 2]);
    float xj = __ldg(&pos[3 * j + 0]);
    float yj = __ldg(&pos[3 * j + 1]);
    float zj = __ldg(&pos[3 * j + 2]);

    // ---- minimum-image wrap, matching jnp.remainder(r + half, box) - half
    float tx = (xi - xj) + hx;
    float ty = (yi - yj) + hy;
    float tz = (zi - zj) + hz;
    tx = tx - floorf(tx / bx) * bx;
    ty = ty - floorf(ty / by) * by;
    tz = tz - floorf(tz / bz) * bz;
    float rx = tx - hx;
    float ry = ty - hy;
    float rz = tz - hz;

    // ---- distance: force non-FMA (x*x + y*y) + z*z to match XLA square+reduce
    float d2 = __fadd_rn(__fadd_rn(__fmul_rn(rx, rx), __fmul_rn(ry, ry)),
                         __fmul_rn(rz, rz));
    float d = sqrtf(d2);
    float m = (d <= 0.5f) ? 1.0f : 0.0f;

    out[p] = make_float4(rx * m, ry * m, rz * m, d * m);
}

extern "C" void kernel_launch(void* const* d_in, const int* in_sizes, int n_in,
                              void* d_out, int out_size)
{
    const float* pos  = (const float*)d_in[0];   // [N, 3] fp32
    const float* boxv = (const float*)d_in[1];   // [3, 3] fp32
    // d_in[2], d_in[3] = i_pairs/j_pairs: intentionally unused (analytic inversion)
    int N       = in_sizes[0] / 3;
    int n_pairs = in_sizes[2];

    float4* out = (float4*)d_out;

    int threads = 256;
    int blocks = (n_pairs + threads - 1) / threads;
    nlist_kernel<<<blocks, threads>>>(pos, boxv, out, n_pairs, N);
}

// round 2
// speedup vs baseline: 1.4503x; 1.4503x over previous
#include <cuda_runtime.h>

// NeighborlistBruteNsq: out[p] = (r_ij, d_ij) * (d_ij <= 0.5), minimum-image
// wrap in an orthogonal box. i_pairs/j_pairs are np.triu_indices(N,1) and are
// NOT read (analytic inversion, saves 67 MB HBM). Round 2: kernel is
// ISSUE-bound (ncu: issue 87.5%, DRAM 24%) -> cut instructions per pair:
//   * fp32 divides replaced by reciprocal multiplies (floor() result is an
//     exact integer; can only differ at |r|~2.5 which is masked on both sides)
//   * triangular-index inversion amortized over 4 pairs per thread
//     (p = blockBase + k*256 + tid keeps stores fully coalesced)

#define PPT 4  // pairs per thread

__global__ __launch_bounds__(256)
void nlist_kernel(const float* __restrict__ pos,
                  const float* __restrict__ boxv,
                  float4* __restrict__ out,
                  int n_pairs, int N)
{
    const int tid  = threadIdx.x;
    int p = blockIdx.x * (256 * PPT) + tid;
    if (p >= n_pairs) return;

    // ---- invert upper-triangular (k=1) flat index once per thread:
    // C(i) = i*(2N-1-i)/2 ; find i with C(i) <= p < C(i+1)
    const int M = 2 * N - 1;
    const float fm = (float)M;
    float disc = fmaxf(fm * fm - 8.0f * (float)p, 0.0f);
    int i = (int)((fm - sqrtf(disc)) * 0.5f);
    i = min(max(i, 0), N - 2);
    #pragma unroll 1
    while (i < N - 2 && (((i + 1) * (M - (i + 1))) >> 1) <= p) ++i;
    #pragma unroll 1
    while (i > 0 && ((i * (M - i)) >> 1) > p) --i;
    int j = i + 1 + (p - ((i * (M - i)) >> 1));

    // ---- box constants (orthogonal box: diagonal entries)
    const float bx = __ldg(&boxv[0]);
    const float by = __ldg(&boxv[4]);
    const float bz = __ldg(&boxv[8]);
    const float hx = bx * 0.5f, hy = by * 0.5f, hz = bz * 0.5f;
    const float ivx = 1.0f / bx, ivy = 1.0f / by, ivz = 1.0f / bz;

    #pragma unroll
    for (int k = 0; k < PPT; ++k) {
        if (p < n_pairs) {
            // positions: 48 KB total, L1 resident
            float xi = __ldg(&pos[3 * i + 0]);
            float yi = __ldg(&pos[3 * i + 1]);
            float zi = __ldg(&pos[3 * i + 2]);
            float xj = __ldg(&pos[3 * j + 0]);
            float yj = __ldg(&pos[3 * j + 1]);
            float zj = __ldg(&pos[3 * j + 2]);

            // min-image wrap: t - floor(t/b)*b with div -> rcp-mul
            // (floor output is an exact integer; value path unchanged)
            float tx = (xi - xj) + hx;
            float ty = (yi - yj) + hy;
            float tz = (zi - zj) + hz;
            float rx = tx - floorf(tx * ivx) * bx - hx;
            float ry = ty - floorf(ty * ivy) * by - hy;
            float rz = tz - floorf(tz * ivz) * bz - hz;

            // distance: non-FMA (x*x + y*y) + z*z to match XLA square+reduce
            float d2 = __fadd_rn(__fadd_rn(__fmul_rn(rx, rx),
                                           __fmul_rn(ry, ry)),
                                 __fmul_rn(rz, rz));
            float d = sqrtf(d2);
            float m = (d <= 0.5f) ? 1.0f : 0.0f;

            __stcs(&out[p], make_float4(rx * m, ry * m, rz * m, d * m));
        }

        // ---- advance by one warp-stride of pairs (256)
        p += 256;
        j += 256;
        #pragma unroll 1
        while (j >= N) {          // crosses <=1-2 rows except in tiny tail
            ++i;
            j = i + 1 + (j - N);
        }
    }
}

extern "C" void kernel_launch(void* const* d_in, const int* in_sizes, int n_in,
                              void* d_out, int out_size)
{
    const float* pos  = (const float*)d_in[0];   // [N,3] fp32
    const float* boxv = (const float*)d_in[1];   // [3,3] fp32
    // d_in[2], d_in[3] (i_pairs/j_pairs) intentionally unused
    int N       = in_sizes[0] / 3;
    int n_pairs = in_sizes[2];

    float4* out = (float4*)d_out;

    int threads = 256;
    int per_block = threads * PPT;
    int blocks = (n_pairs + per_block - 1) / per_block;
    nlist_kernel<<<blocks, threads>>>(pos, boxv, out, n_pairs, N);
}

// round 3
// speedup vs baseline: 1.4868x; 1.0252x over previous
#include <cuda_runtime.h>

// NeighborlistBruteNsq, round 3: row-per-block layout.
// ncu r2: issue 82%, DRAM 36% -> still instruction-bound. Eliminate the
// per-thread triangular inversion and row-advance loop entirely by making
// the row index i block-uniform: block b handles rows b and rows-1-b
// (lengths sum to N -> perfectly balanced, 2048 blocks x 4096 pairs).
// i-row position is loaded once per row; j and p advance by +256.
// All fp expressions identical to the passing r2 kernel (no mask flips).

__device__ __forceinline__
void do_row(int i, int N,
            const float* __restrict__ pos,
            float bx, float by, float bz,
            float hx, float hy, float hz,
            float ivx, float ivy, float ivz,
            float4* __restrict__ out)
{
    const int M    = 2 * N - 1;
    const int base = (i * (M - i)) >> 1;   // pairs before row i
    const int len  = N - 1 - i;            // pairs in row i

    // i-row position: block-uniform, loaded once
    const float xi = __ldg(&pos[3 * i + 0]);
    const float yi = __ldg(&pos[3 * i + 1]);
    const float zi = __ldg(&pos[3 * i + 2]);

    #pragma unroll 4
    for (int t = threadIdx.x; t < len; t += 256) {
        const int j = i + 1 + t;

        const float xj = __ldg(&pos[3 * j + 0]);
        const float yj = __ldg(&pos[3 * j + 1]);
        const float zj = __ldg(&pos[3 * j + 2]);

        // min-image wrap (identical expressions to the passing kernel)
        float tx = (xi - xj) + hx;
        float ty = (yi - yj) + hy;
        float tz = (zi - zj) + hz;
        float rx = tx - floorf(tx * ivx) * bx - hx;
        float ry = ty - floorf(ty * ivy) * by - hy;
        float rz = tz - floorf(tz * ivz) * bz - hz;

        // non-FMA (x*x + y*y) + z*z to match XLA square+reduce
        float d2 = __fadd_rn(__fadd_rn(__fmul_rn(rx, rx),
                                       __fmul_rn(ry, ry)),
                             __fmul_rn(rz, rz));
        float d = sqrtf(d2);
        float m = (d <= 0.5f) ? 1.0f : 0.0f;

        __stcs(&out[base + t], make_float4(rx * m, ry * m, rz * m, d * m));
    }
}

__global__ __launch_bounds__(256)
void nlist_kernel(const float* __restrict__ pos,
                  const float* __restrict__ boxv,
                  float4* __restrict__ out, int N)
{
    const int rows = N - 1;          // rows 0 .. N-2
    const int r1   = blockIdx.x;
    const int r2   = rows - 1 - r1;  // complementary row (len r1 + len r2 = N)

    const float bx = __ldg(&boxv[0]);
    const float by = __ldg(&boxv[4]);
    const float bz = __ldg(&boxv[8]);
    const float hx = bx * 0.5f, hy = by * 0.5f, hz = bz * 0.5f;
    const float ivx = 1.0f / bx, ivy = 1.0f / by, ivz = 1.0f / bz;

    do_row(r1, N, pos, bx, by, bz, hx, hy, hz, ivx, ivy, ivz, out);
    if (r2 > r1)
        do_row(r2, N, pos, bx, by, bz, hx, hy, hz, ivx, ivy, ivz, out);
}

extern "C" void kernel_launch(void* const* d_in, const int* in_sizes, int n_in,
                              void* d_out, int out_size)
{
    const float* pos  = (const float*)d_in[0];   // [N,3] fp32
    const float* boxv = (const float*)d_in[1];   // [3,3] fp32
    // d_in[2], d_in[3] (i_pairs/j_pairs) intentionally unused: analytic layout
    int N = in_sizes[0] / 3;

    float4* out = (float4*)d_out;

    int rows   = N - 1;
    int blocks = (rows + 1) / 2;     // paired rows -> balanced blocks
    nlist_kernel<<<blocks, 256>>>(pos, boxv, out, N);
}